// round 1
// baseline (speedup 1.0000x reference)
#include <cuda_runtime.h>
#include <cuda_bf16.h>

// Problem constants: x [8,256,128,128] f32, params [8,512] f32, W [256,512] f32
#define B_   8
#define C_   256
#define HW_  16384           // 128*128
#define CHW_ 4194304         // 256*16384
#define EPS_ 1e-5f

// -------- scratch (__device__ globals; no allocation allowed) --------
__device__ float g_csum[B_ * C_];     // per (b,c) sum over HW
__device__ float g_csumsq[B_ * C_];   // per (b,c) sum of squares
__device__ float g_Wt[2 * C_ * C_];   // W transposed: Wt[i][o] = W[o][i], i in [0,512)
__device__ float g_A[B_ * C_ * C_];   // effective weight, K-major: A[b][c][o]
__device__ float g_dd[B_ * C_];       // effective bias d[b][o]

__inline__ __device__ float warpReduceSum(float v) {
    #pragma unroll
    for (int o = 16; o > 0; o >>= 1) v += __shfl_down_sync(0xffffffffu, v, o);
    return v;
}

// -------- kernel 1: per-(b,c) sum / sumsq over the 16384-pixel plane --------
__global__ __launch_bounds__(256) void stats_kernel(const float* __restrict__ x) {
    const int c = blockIdx.x;
    const int b = blockIdx.y;
    const float4* p = (const float4*)(x + ((size_t)b * C_ + c) * HW_);
    float s = 0.f, ss = 0.f;
    for (int i = threadIdx.x; i < HW_ / 4; i += 256) {
        float4 v = p[i];
        s  += v.x + v.y + v.z + v.w;
        ss += v.x * v.x + v.y * v.y + v.z * v.z + v.w * v.w;
    }
    __shared__ float rs[8], rss[8];
    float ws  = warpReduceSum(s);
    float wss = warpReduceSum(ss);
    int lane = threadIdx.x & 31, warp = threadIdx.x >> 5;
    if (lane == 0) { rs[warp] = ws; rss[warp] = wss; }
    __syncthreads();
    if (threadIdx.x == 0) {
        float ts = 0.f, tss = 0.f;
        #pragma unroll
        for (int w = 0; w < 8; w++) { ts += rs[w]; tss += rss[w]; }
        g_csum[b * C_ + c]   = ts;
        g_csumsq[b * C_ + c] = tss;
    }
}

// -------- kernel 2: transpose W [256,512] -> Wt [512,256] (coalesced writes) ----
__global__ __launch_bounds__(256) void transpose_kernel(const float* __restrict__ W) {
    const int i = blockIdx.x;      // 0..511  (input-channel index of the 2C dim)
    const int o = threadIdx.x;     // 0..255  (output channel)
    g_Wt[i * C_ + o] = W[o * (2 * C_) + i];
}

// -------- kernel 3: per-batch prep — build A (K-major) and d ---------------------
__global__ __launch_bounds__(256) void prep_kernel(const float* __restrict__ params) {
    const int b = blockIdx.x;
    const int t = threadIdx.x;     // doubles as channel index and output index

    __shared__ float sm_m[C_], sm_r[C_];
    __shared__ float rs[8], rss[8];
    __shared__ float sM, sR;

    float cs  = g_csum[b * C_ + t];
    float css = g_csumsq[b * C_ + t];
    float mean = cs * (1.f / HW_);
    float var  = css * (1.f / HW_) - mean * mean;
    sm_m[t] = mean;
    sm_r[t] = rsqrtf(var + EPS_);

    // reduce channel sums -> LayerNorm stats over C*H*W
    float ws  = warpReduceSum(cs);
    float wss = warpReduceSum(css);
    int lane = t & 31, warp = t >> 5;
    if (lane == 0) { rs[warp] = ws; rss[warp] = wss; }
    __syncthreads();
    if (t == 0) {
        float ts = 0.f, tss = 0.f;
        #pragma unroll
        for (int w = 0; w < 8; w++) { ts += rs[w]; tss += rss[w]; }
        float M = ts * (1.f / CHW_);
        float V = tss * (1.f / CHW_) - M * M;
        sM = M;
        sR = rsqrtf(V + EPS_);
    }
    __syncthreads();
    const float M = sM, R = sR;

    const int o = t;
    const float gamma = params[b * 2 * C_ + o];
    const float beta  = params[b * 2 * C_ + C_ + o];

    float acc_md = 0.f, acc_w2 = 0.f;
    float* Ab = g_A + (size_t)b * C_ * C_;   // layout [c][o]
    #pragma unroll 4
    for (int c = 0; c < C_; c++) {
        float w1 = g_Wt[c * C_ + o];          // W[o][c]      (coalesced in o)
        float w2 = g_Wt[(C_ + c) * C_ + o];   // W[o][C+c]    (coalesced in o)
        float r = sm_r[c], m = sm_m[c];
        acc_md += w1 * r * m;
        acc_w2 += w2;
        Ab[c * C_ + o] = gamma * (w1 * r + w2 * R);   // coalesced write
    }
    g_dd[b * C_ + o] = gamma * (-acc_md - M * R * acc_w2) + beta;
}

// -------- kernel 4: batched GEMM  out[b] = A[b]^T(K-major) @ x[b] + d[b] --------
// A: [K=256][M=256] (K-major), X: [K=256][N=16384], O: [M=256][N=16384]
// Tiles: BM=128, BN=128, BK=8; 256 threads; 8x8 microtile; double-buffered smem.
__global__ __launch_bounds__(256, 2) void gemm_kernel(const float* __restrict__ x,
                                                      float* __restrict__ out) {
    const int b  = blockIdx.z;
    const int m0 = blockIdx.y * 128;
    const int n0 = blockIdx.x * 128;

    const float* __restrict__ A = g_A + (size_t)b * C_ * C_;
    const float* __restrict__ X = x   + (size_t)b * CHW_;
    float*       __restrict__ O = out + (size_t)b * CHW_;

    __shared__ float As[2][8][128];
    __shared__ float Bs[2][8][128];

    const int tid  = threadIdx.x;
    const int lrow = tid >> 5;            // 0..7   (k within tile)
    const int lcol = (tid & 31) << 2;     // 0..124 (float4 column)
    const int ty   = tid >> 4;            // 0..15  -> m microtile
    const int tx   = tid & 15;            // 0..15  -> n microtile

    float acc[8][8];
    #pragma unroll
    for (int i = 0; i < 8; i++)
        #pragma unroll
        for (int j = 0; j < 8; j++) acc[i][j] = 0.f;

    const float* Ag = A + lrow * C_ + m0 + lcol;
    const float* Xg = X + (size_t)lrow * HW_ + n0 + lcol;

    // prologue: tile 0
    {
        float4 a0 = *(const float4*)Ag;
        float4 b0 = *(const float4*)Xg;
        *(float4*)&As[0][lrow][lcol] = a0;
        *(float4*)&Bs[0][lrow][lcol] = b0;
    }
    __syncthreads();

    int buf = 0;
    for (int k0 = 0; k0 < C_; k0 += 8) {
        float4 an, bn;
        const bool has_next = (k0 + 8) < C_;
        if (has_next) {
            an = *(const float4*)(Ag + (k0 + 8) * C_);
            bn = *(const float4*)(Xg + (size_t)(k0 + 8) * HW_);
        }
        #pragma unroll
        for (int kk = 0; kk < 8; kk++) {
            float ar[8], br[8];
            *(float4*)&ar[0] = *(const float4*)&As[buf][kk][ty * 8];
            *(float4*)&ar[4] = *(const float4*)&As[buf][kk][ty * 8 + 4];
            *(float4*)&br[0] = *(const float4*)&Bs[buf][kk][tx * 8];
            *(float4*)&br[4] = *(const float4*)&Bs[buf][kk][tx * 8 + 4];
            #pragma unroll
            for (int i = 0; i < 8; i++)
                #pragma unroll
                for (int j = 0; j < 8; j++)
                    acc[i][j] = fmaf(ar[i], br[j], acc[i][j]);
        }
        if (has_next) {
            *(float4*)&As[buf ^ 1][lrow][lcol] = an;
            *(float4*)&Bs[buf ^ 1][lrow][lcol] = bn;
        }
        __syncthreads();
        buf ^= 1;
    }

    // epilogue: add effective bias, store
    #pragma unroll
    for (int i = 0; i < 8; i++) {
        const int m = m0 + ty * 8 + i;
        const float dv = g_dd[b * C_ + m];
        float* op = O + (size_t)m * HW_ + n0 + tx * 8;
        float4 o0, o1;
        o0.x = acc[i][0] + dv; o0.y = acc[i][1] + dv;
        o0.z = acc[i][2] + dv; o0.w = acc[i][3] + dv;
        o1.x = acc[i][4] + dv; o1.y = acc[i][5] + dv;
        o1.z = acc[i][6] + dv; o1.w = acc[i][7] + dv;
        *(float4*)(op)     = o0;
        *(float4*)(op + 4) = o1;
    }
}

extern "C" void kernel_launch(void* const* d_in, const int* in_sizes, int n_in,
                              void* d_out, int out_size) {
    const float* x      = (const float*)d_in[0];   // [8,256,128,128]
    const float* params = (const float*)d_in[1];   // [8,512]
    const float* W      = (const float*)d_in[2];   // [256,512]
    float* out          = (float*)d_out;

    stats_kernel<<<dim3(C_, B_), 256>>>(x);
    transpose_kernel<<<2 * C_, 256>>>(W);
    prep_kernel<<<B_, 256>>>(params);
    gemm_kernel<<<dim3(HW_ / 128, C_ / 128, B_), 256>>>(x, out);
}

// round 4
// speedup vs baseline: 1.6962x; 1.6962x over previous
#include <cuda_runtime.h>
#include <cuda_bf16.h>
#include <cstdint>

#define B_   8
#define C_   256
#define HW_  16384
#define EPS_ 1e-5f

// ---------------- device scratch (static; no allocation APIs) ----------------
__device__ __nv_bfloat16 g_xh[(size_t)B_ * HW_ * C_];   // x hi, [b][hw][c]
__device__ __nv_bfloat16 g_xl[(size_t)B_ * HW_ * C_];   // x lo, [b][hw][c]
__device__ __nv_bfloat16 g_Ah[B_ * C_ * C_];            // A hi, [b][o][c]
__device__ __nv_bfloat16 g_Al[B_ * C_ * C_];            // A lo, [b][o][c]
__device__ float g_Wt[2 * C_ * C_];                     // W^T
__device__ float g_psum[B_ * 128 * C_];                 // per (b, hwtile, c)
__device__ float g_psumsq[B_ * 128 * C_];
__device__ float g_dd[B_ * C_];                         // folded bias

// ---------------- helpers (sm_80-era instructions only; no 'a' features) -----
__device__ __forceinline__ uint32_t smem_u32(const void* p) {
    uint32_t a;
    asm("{ .reg .u64 t; cvta.to.shared.u64 t, %1; cvt.u32.u64 %0, t; }" : "=r"(a) : "l"(p));
    return a;
}
__device__ __forceinline__ void cp16(uint32_t s, const void* g) {
    asm volatile("cp.async.cg.shared.global [%0], [%1], 16;" :: "r"(s), "l"(g) : "memory");
}
#define CP_COMMIT() asm volatile("cp.async.commit_group;" ::: "memory")
#define CP_WAIT1()  asm volatile("cp.async.wait_group 1;" ::: "memory")

__device__ __forceinline__ void ldm4(uint32_t r[4], uint32_t addr) {
    asm volatile("ldmatrix.sync.aligned.m8n8.x4.shared.b16 {%0,%1,%2,%3}, [%4];"
                 : "=r"(r[0]), "=r"(r[1]), "=r"(r[2]), "=r"(r[3]) : "r"(addr));
}
__device__ __forceinline__ void mma_bf16(float d[4], const uint32_t a[4], const uint32_t* b) {
    asm volatile("mma.sync.aligned.m16n8k16.row.col.f32.bf16.bf16.f32 "
                 "{%0,%1,%2,%3}, {%4,%5,%6,%7}, {%8,%9}, {%0,%1,%2,%3};"
                 : "+f"(d[0]), "+f"(d[1]), "+f"(d[2]), "+f"(d[3])
                 : "r"(a[0]), "r"(a[1]), "r"(a[2]), "r"(a[3]), "r"(b[0]), "r"(b[1]));
}
__device__ __forceinline__ uint32_t pack_bf2(__nv_bfloat16 a, __nv_bfloat16 b) {
    return (uint32_t)__bfloat16_as_ushort(a) | ((uint32_t)__bfloat16_as_ushort(b) << 16);
}

// ---- kernel 1: fused stats-partials + bf16 hi/lo split + transpose to [b][hw][c]
__global__ __launch_bounds__(256) void conv_kernel(const float* __restrict__ x) {
    const int b = blockIdx.z, c0 = blockIdx.y * 64, hw0 = blockIdx.x * 128;
    __shared__ float stg[64 * 133];
    __shared__ float red_s[256], red_q[256];
    const int t = threadIdx.x;
    const int ci = t >> 2, sub = t & 3;

    const float4* src = (const float4*)(x + ((size_t)(b * C_ + c0 + ci)) * HW_ + hw0);
    float s = 0.f, q = 0.f;
    #pragma unroll
    for (int j = 0; j < 8; j++) {
        const int h4 = sub + 4 * j;
        float4 v = src[h4];
        float* d = &stg[ci * 133 + h4 * 4];
        d[0] = v.x; d[1] = v.y; d[2] = v.z; d[3] = v.w;
        s += v.x + v.y + v.z + v.w;
        q += v.x * v.x + v.y * v.y + v.z * v.z + v.w * v.w;
    }
    red_s[t] = s; red_q[t] = q;
    __syncthreads();
    if (t < 64) {
        float ps = red_s[4 * t] + red_s[4 * t + 1] + red_s[4 * t + 2] + red_s[4 * t + 3];
        float pq = red_q[4 * t] + red_q[4 * t + 1] + red_q[4 * t + 2] + red_q[4 * t + 3];
        g_psum[(b * 128 + blockIdx.x) * C_ + c0 + t]   = ps;
        g_psumsq[(b * 128 + blockIdx.x) * C_ + c0 + t] = pq;
    }
    const int wid = t >> 5, lane = t & 31;
    uint32_t* oh = (uint32_t*)g_xh;
    uint32_t* ol = (uint32_t*)g_xl;
    #pragma unroll
    for (int i = 0; i < 16; i++) {
        const int hj = wid + 8 * i;
        float a0 = stg[(2 * lane) * 133 + hj];
        float a1 = stg[(2 * lane + 1) * 133 + hj];
        __nv_bfloat16 h0 = __float2bfloat16(a0);
        __nv_bfloat16 l0 = __float2bfloat16(a0 - __bfloat162float(h0));
        __nv_bfloat16 h1 = __float2bfloat16(a1);
        __nv_bfloat16 l1 = __float2bfloat16(a1 - __bfloat162float(h1));
        const size_t base = ((size_t)b * HW_ + hw0 + hj) * C_ + c0;   // even
        oh[(base >> 1) + lane] = pack_bf2(h0, h1);
        ol[(base >> 1) + lane] = pack_bf2(l0, l1);
    }
}

// ---- kernel 2: transpose W -> Wt (coalesced) ----
__global__ __launch_bounds__(256) void transpose_kernel(const float* __restrict__ W) {
    g_Wt[blockIdx.x * C_ + threadIdx.x] = W[threadIdx.x * (2 * C_) + blockIdx.x];
}

__inline__ __device__ float warpSum(float v) {
    #pragma unroll
    for (int o = 16; o > 0; o >>= 1) v += __shfl_down_sync(0xffffffffu, v, o);
    return v;
}

// ---- kernel 3: reduce partials, build A hi/lo (bf16) + folded bias ----
__global__ __launch_bounds__(256) void prep_kernel(const float* __restrict__ params) {
    const int b = blockIdx.x, t = threadIdx.x;
    float cs = 0.f, cq = 0.f;
    for (int i = 0; i < 128; i++) {
        cs += g_psum[(b * 128 + i) * C_ + t];
        cq += g_psumsq[(b * 128 + i) * C_ + t];
    }
    __shared__ float sm_m[C_], sm_r[C_], rs[8], rq[8];
    __shared__ float sM, sR;
    float mean = cs * (1.f / HW_);
    float var  = cq * (1.f / HW_) - mean * mean;
    sm_m[t] = mean;
    sm_r[t] = rsqrtf(var + EPS_);
    float ws = warpSum(cs), wq = warpSum(cq);
    int lane = t & 31, warp = t >> 5;
    if (lane == 0) { rs[warp] = ws; rq[warp] = wq; }
    __syncthreads();
    if (t == 0) {
        float ts = 0.f, tq = 0.f;
        #pragma unroll
        for (int w = 0; w < 8; w++) { ts += rs[w]; tq += rq[w]; }
        float M = ts / (float)((size_t)C_ * HW_);
        float V = tq / (float)((size_t)C_ * HW_) - M * M;
        sM = M; sR = rsqrtf(V + EPS_);
    }
    __syncthreads();
    const float M = sM, R = sR;
    const int o = t;
    const float gamma = params[b * 2 * C_ + o];
    const float beta  = params[b * 2 * C_ + C_ + o];
    float accmd = 0.f, accw2 = 0.f;
    uint32_t* ah = (uint32_t*)g_Ah;
    uint32_t* al = (uint32_t*)g_Al;
    for (int c = 0; c < C_; c += 2) {
        float w1a = g_Wt[c * C_ + o],       w2a = g_Wt[(C_ + c) * C_ + o];
        float w1b = g_Wt[(c + 1) * C_ + o], w2b = g_Wt[(C_ + c + 1) * C_ + o];
        float ra = sm_r[c], ma = sm_m[c], rb = sm_r[c + 1], mb = sm_m[c + 1];
        accmd += w1a * ra * ma + w1b * rb * mb;
        accw2 += w2a + w2b;
        float Aa = gamma * (w1a * ra + w2a * R);
        float Ab = gamma * (w1b * rb + w2b * R);
        __nv_bfloat16 hA = __float2bfloat16(Aa);
        __nv_bfloat16 lA = __float2bfloat16(Aa - __bfloat162float(hA));
        __nv_bfloat16 hB = __float2bfloat16(Ab);
        __nv_bfloat16 lB = __float2bfloat16(Ab - __bfloat162float(hB));
        size_t bi = (((size_t)(b * C_ + o)) * C_ + c) >> 1;
        ah[bi] = pack_bf2(hA, hB);
        al[bi] = pack_bf2(lA, lB);
    }
    g_dd[b * C_ + o] = gamma * (-accmd - M * R * accw2) + beta;
}

// ---- kernel 4: mma.sync bf16 GEMM, 3-term split, 3-stage cp.async pipeline ----
// CTA: M=128, N=256, Kchunk=32. 8 warps (2m x 4n), warp tile 64x64.
// smem per stage: Ah[128][40] Al[128][40] Bh[256][40] Bl[256][40] bf16 (40=32+8 pad)
#define RS_      80              // row stride bytes (40 bf16)
#define A_HALF   10240           // 128*80
#define B_HALF   20480           // 256*80
#define STAGE_   61440           // 2*A_HALF + 2*B_HALF
#define NSTAGE_  3
#define SMEM_BYTES (STAGE_ * NSTAGE_)   // 184320

__global__ __launch_bounds__(256, 1) void gemm_kernel(float* __restrict__ out) {
    extern __shared__ char dsm[];
    const uint32_t sbase = smem_u32(dsm);

    const int b  = blockIdx.z;
    const int m0 = blockIdx.y * 128;
    const int n0 = blockIdx.x * 256;
    const int t  = threadIdx.x, wid = t >> 5, lane = t & 31;
    const int m64w = (wid & 1) * 64;
    const int n64w = (wid >> 1) * 64;

    const char* pAh = (const char*)(g_Ah + ((size_t)b * C_ + m0) * C_);
    const char* pAl = (const char*)(g_Al + ((size_t)b * C_ + m0) * C_);
    const char* pBh = (const char*)(g_xh + ((size_t)b * HW_ + n0) * C_);
    const char* pBl = (const char*)(g_xl + ((size_t)b * HW_ + n0) * C_);

    // per-thread chunk decomposition (precompute row/c4 per section)
    auto load_stage = [&](int kc, int s) {
        const uint32_t st = sbase + s * STAGE_;
        const int k0b = kc * 64;     // 32 bf16 = 64 bytes along c
        #pragma unroll
        for (int i = 0; i < 4; i++) {          // A: 1024 chunks (hi 512, lo 512)
            const int ch = t + i * 256;
            const int half = ch >> 9, cc = ch & 511;
            const int row = cc >> 2, c4 = cc & 3;
            const char* g = (half ? pAl : pAh) + row * 512 + k0b + c4 * 16;
            cp16(st + half * A_HALF + row * RS_ + c4 * 16, g);
        }
        #pragma unroll
        for (int i = 0; i < 8; i++) {          // B: 2048 chunks (hi 1024, lo 1024)
            const int ch = t + i * 256;
            const int half = ch >> 10, cc = ch & 1023;
            const int row = cc >> 2, c4 = cc & 3;
            const char* g = (half ? pBl : pBh) + row * 512 + k0b + c4 * 16;
            cp16(st + 2 * A_HALF + half * B_HALF + row * RS_ + c4 * 16, g);
        }
    };

    float acc[4][8][4];
    #pragma unroll
    for (int i = 0; i < 4; i++)
        #pragma unroll
        for (int j = 0; j < 8; j++)
            #pragma unroll
            for (int e = 0; e < 4; e++) acc[i][j][e] = 0.f;

    load_stage(0, 0); CP_COMMIT();
    load_stage(1, 1); CP_COMMIT();

    for (int kc = 0; kc < 8; kc++) {
        CP_WAIT1();
        __syncthreads();
        const uint32_t st = sbase + (kc % NSTAGE_) * STAGE_;

        #pragma unroll
        for (int kk = 0; kk < 2; kk++) {
            const int k16b = kk * 32;      // 16 bf16 = 32 bytes
            uint32_t ah[4][4], al[4][4], bh[4][4], bl[4][4];
            const uint32_t aoff = st + (uint32_t)(m64w + (lane & 15)) * RS_
                                + k16b + ((lane >> 4) * 16);
            #pragma unroll
            for (int mt = 0; mt < 4; mt++) {
                ldm4(ah[mt], aoff + mt * 16 * RS_);
                ldm4(al[mt], aoff + A_HALF + mt * 16 * RS_);
            }
            const uint32_t boff = st + 2 * A_HALF
                                + (uint32_t)(n64w + (lane & 7) + ((lane >> 4) << 3)) * RS_
                                + k16b + (((lane >> 3) & 1) * 16);
            #pragma unroll
            for (int tp = 0; tp < 4; tp++) {
                ldm4(bh[tp], boff + tp * 16 * RS_);
                ldm4(bl[tp], boff + B_HALF + tp * 16 * RS_);
            }
            #pragma unroll
            for (int mt = 0; mt < 4; mt++) {
                #pragma unroll
                for (int tp = 0; tp < 4; tp++) {
                    mma_bf16(acc[mt][2 * tp],     ah[mt], &bh[tp][0]);
                    mma_bf16(acc[mt][2 * tp + 1], ah[mt], &bh[tp][2]);
                    mma_bf16(acc[mt][2 * tp],     ah[mt], &bl[tp][0]);
                    mma_bf16(acc[mt][2 * tp + 1], ah[mt], &bl[tp][2]);
                    mma_bf16(acc[mt][2 * tp],     al[mt], &bh[tp][0]);
                    mma_bf16(acc[mt][2 * tp + 1], al[mt], &bh[tp][2]);
                }
            }
        }
        if (kc + 2 < 8) load_stage(kc + 2, (kc + 2) % NSTAGE_);
        CP_COMMIT();
    }

    // epilogue: direct stores; 4-lane groups cover aligned 32B sectors
    #pragma unroll
    for (int mt = 0; mt < 4; mt++) {
        const int o = m0 + m64w + mt * 16 + (lane >> 2);
        const float dv0 = g_dd[b * C_ + o];
        const float dv8 = g_dd[b * C_ + o + 8];
        float* r0 = out + ((size_t)(b * C_ + o)) * HW_;
        float* r8 = out + ((size_t)(b * C_ + o + 8)) * HW_;
        #pragma unroll
        for (int n = 0; n < 8; n++) {
            const int hw = n0 + n64w + n * 8 + (lane & 3) * 2;
            float2 v0, v1;
            v0.x = acc[mt][n][0] + dv0; v0.y = acc[mt][n][1] + dv0;
            v1.x = acc[mt][n][2] + dv8; v1.y = acc[mt][n][3] + dv8;
            *(float2*)(r0 + hw) = v0;
            *(float2*)(r8 + hw) = v1;
        }
    }
}

extern "C" void kernel_launch(void* const* d_in, const int* in_sizes, int n_in,
                              void* d_out, int out_size) {
    const float* x      = (const float*)d_in[0];
    const float* params = (const float*)d_in[1];
    const float* W      = (const float*)d_in[2];
    float* out          = (float*)d_out;

    cudaFuncSetAttribute(gemm_kernel, cudaFuncAttributeMaxDynamicSharedMemorySize, SMEM_BYTES);

    conv_kernel<<<dim3(128, 4, B_), 256>>>(x);
    transpose_kernel<<<2 * C_, 256>>>(W);
    prep_kernel<<<B_, 256>>>(params);
    gemm_kernel<<<dim3(HW_ / 256, C_ / 128, B_), 256, SMEM_BYTES>>>(out);
}

// round 5
// speedup vs baseline: 1.7776x; 1.0480x over previous
#include <cuda_runtime.h>
#include <cuda_bf16.h>
#include <cstdint>

#define B_   8
#define C_   256
#define HW_  16384
#define CHW_ 4194304
#define EPS_ 1e-5f

// ---------------- device scratch (static; no allocation APIs) ----------------
__device__ __nv_bfloat16 g_Ah[B_ * C_ * C_];   // A hi, [b][o][c]
__device__ __nv_bfloat16 g_Al[B_ * C_ * C_];   // A lo, [b][o][c]
__device__ float g_Wt[2 * C_ * C_];            // W^T
__device__ float g_csum[B_ * C_];
__device__ float g_csumsq[B_ * C_];
__device__ float g_dd[B_ * C_];                // folded bias

// ---------------- helpers (sm_80-era instructions only) ----------------
__device__ __forceinline__ uint32_t smem_u32(const void* p) {
    uint32_t a;
    asm("{ .reg .u64 t; cvta.to.shared.u64 t, %1; cvt.u32.u64 %0, t; }" : "=r"(a) : "l"(p));
    return a;
}
__device__ __forceinline__ void cp16(uint32_t s, const void* g) {
    asm volatile("cp.async.cg.shared.global [%0], [%1], 16;" :: "r"(s), "l"(g) : "memory");
}
#define CP_COMMIT() asm volatile("cp.async.commit_group;" ::: "memory")
#define CP_WAIT1()  asm volatile("cp.async.wait_group 1;" ::: "memory")

__device__ __forceinline__ void ldm4(uint32_t r[4], uint32_t addr) {
    asm volatile("ldmatrix.sync.aligned.m8n8.x4.shared.b16 {%0,%1,%2,%3}, [%4];"
                 : "=r"(r[0]), "=r"(r[1]), "=r"(r[2]), "=r"(r[3]) : "r"(addr));
}
__device__ __forceinline__ void ldm4t(uint32_t r[4], uint32_t addr) {
    asm volatile("ldmatrix.sync.aligned.m8n8.x4.trans.shared.b16 {%0,%1,%2,%3}, [%4];"
                 : "=r"(r[0]), "=r"(r[1]), "=r"(r[2]), "=r"(r[3]) : "r"(addr));
}
__device__ __forceinline__ void mma_bf16(float d[4], const uint32_t a[4], const uint32_t* b) {
    asm volatile("mma.sync.aligned.m16n8k16.row.col.f32.bf16.bf16.f32 "
                 "{%0,%1,%2,%3}, {%4,%5,%6,%7}, {%8,%9}, {%0,%1,%2,%3};"
                 : "+f"(d[0]), "+f"(d[1]), "+f"(d[2]), "+f"(d[3])
                 : "r"(a[0]), "r"(a[1]), "r"(a[2]), "r"(a[3]), "r"(b[0]), "r"(b[1]));
}
__device__ __forceinline__ uint32_t pack_bf2(__nv_bfloat16 a, __nv_bfloat16 b) {
    return (uint32_t)__bfloat16_as_ushort(a) | ((uint32_t)__bfloat16_as_ushort(b) << 16);
}
__device__ __forceinline__ void split2(float a, float b, uint32_t& h, uint32_t& l) {
    __nv_bfloat162 hp = __floats2bfloat162_rn(a, b);   // .x=a(lo half), .y=b(hi half)
    h = *reinterpret_cast<uint32_t*>(&hp);
    float la = a - __bfloat162float(hp.x);
    float lb = b - __bfloat162float(hp.y);
    __nv_bfloat162 lp = __floats2bfloat162_rn(la, lb);
    l = *reinterpret_cast<uint32_t*>(&lp);
}

__inline__ __device__ float warpSum(float v) {
    #pragma unroll
    for (int o = 16; o > 0; o >>= 1) v += __shfl_down_sync(0xffffffffu, v, o);
    return v;
}

// ---- kernel 1: per-(b,c) sum / sumsq over the plane ----
__global__ __launch_bounds__(256) void stats_kernel(const float* __restrict__ x) {
    const int c = blockIdx.x, b = blockIdx.y;
    const float4* p = (const float4*)(x + ((size_t)b * C_ + c) * HW_);
    float s = 0.f, q = 0.f;
    for (int i = threadIdx.x; i < HW_ / 4; i += 256) {
        float4 v = p[i];
        s += v.x + v.y + v.z + v.w;
        q += v.x * v.x + v.y * v.y + v.z * v.z + v.w * v.w;
    }
    __shared__ float rs[8], rq[8];
    float ws = warpSum(s), wq = warpSum(q);
    int lane = threadIdx.x & 31, warp = threadIdx.x >> 5;
    if (lane == 0) { rs[warp] = ws; rq[warp] = wq; }
    __syncthreads();
    if (threadIdx.x == 0) {
        float ts = 0.f, tq = 0.f;
        #pragma unroll
        for (int w = 0; w < 8; w++) { ts += rs[w]; tq += rq[w]; }
        g_csum[b * C_ + c] = ts;
        g_csumsq[b * C_ + c] = tq;
    }
}

// ---- kernel 2: transpose W -> Wt ----
__global__ __launch_bounds__(256) void transpose_kernel(const float* __restrict__ W) {
    g_Wt[blockIdx.x * C_ + threadIdx.x] = W[threadIdx.x * (2 * C_) + blockIdx.x];
}

// ---- kernel 3: build A hi/lo (bf16) + folded bias ----
__global__ __launch_bounds__(256) void prep_kernel(const float* __restrict__ params) {
    const int b = blockIdx.x, t = threadIdx.x;
    const float cs = g_csum[b * C_ + t];
    const float cq = g_csumsq[b * C_ + t];
    __shared__ float sm_m[C_], sm_r[C_], rs[8], rq[8];
    __shared__ float sM, sR;
    float mean = cs * (1.f / HW_);
    float var  = cq * (1.f / HW_) - mean * mean;
    sm_m[t] = mean;
    sm_r[t] = rsqrtf(var + EPS_);
    float ws = warpSum(cs), wq = warpSum(cq);
    int lane = t & 31, warp = t >> 5;
    if (lane == 0) { rs[warp] = ws; rq[warp] = wq; }
    __syncthreads();
    if (t == 0) {
        float ts = 0.f, tq = 0.f;
        #pragma unroll
        for (int w = 0; w < 8; w++) { ts += rs[w]; tq += rq[w]; }
        float M = ts / (float)CHW_;
        float V = tq / (float)CHW_ - M * M;
        sM = M; sR = rsqrtf(V + EPS_);
    }
    __syncthreads();
    const float M = sM, R = sR;
    const int o = t;
    const float gamma = params[b * 2 * C_ + o];
    const float beta  = params[b * 2 * C_ + C_ + o];
    float accmd = 0.f, accw2 = 0.f;
    uint32_t* ah = (uint32_t*)g_Ah;
    uint32_t* al = (uint32_t*)g_Al;
    for (int c = 0; c < C_; c += 2) {
        float w1a = g_Wt[c * C_ + o],       w2a = g_Wt[(C_ + c) * C_ + o];
        float w1b = g_Wt[(c + 1) * C_ + o], w2b = g_Wt[(C_ + c + 1) * C_ + o];
        float ra = sm_r[c], ma = sm_m[c], rb = sm_r[c + 1], mb = sm_m[c + 1];
        accmd += w1a * ra * ma + w1b * rb * mb;
        accw2 += w2a + w2b;
        float Aa = gamma * (w1a * ra + w2a * R);
        float Ab = gamma * (w1b * rb + w2b * R);
        uint32_t hh, ll;
        split2(Aa, Ab, hh, ll);
        size_t bi = (((size_t)(b * C_ + o)) * C_ + c) >> 1;
        ah[bi] = hh;
        al[bi] = ll;
    }
    g_dd[b * C_ + o] = gamma * (-accmd - M * R * accw2) + beta;
}

// ---- kernel 4: fused convert+GEMM --------------------------------------------
// CTA: M=128, N=256, Kchunk=32. 8 warps (2m x 4n), warp tile 64x64.
// smem: fp32 B staging x3 (32KB each) | A hi/lo bf16 x3 stages (20KB each)
//       | converted Bh/Bl bf16 x2 sets (33KB each, rows k x 528B)
#define STG_STRIDE  32768
#define A_STAGE_OFF 98304
#define A_STRIDE    20480
#define CONV_OFF    159744
#define CONV_SET    33792
#define CONV_HALF   16896
#define SMEM_BYTES  227328

__global__ __launch_bounds__(256, 1) void gemm_kernel(const float* __restrict__ x,
                                                      float* __restrict__ out) {
    extern __shared__ char dsm[];
    const uint32_t sb = smem_u32(dsm);
    const int b = blockIdx.z, m0 = blockIdx.y * 128, n0 = blockIdx.x * 256;
    const int t = threadIdx.x, wid = t >> 5, lane = t & 31;
    const int m64w = (wid & 1) * 64, n64w = (wid >> 1) * 64;

    const char* xb  = (const char*)(x + (size_t)b * CHW_ + n0);
    const char* pAh = (const char*)(g_Ah + ((size_t)(b * C_ + m0)) * C_);
    const char* pAl = (const char*)(g_Al + ((size_t)(b * C_ + m0)) * C_);

    auto load_group = [&](int kcc) {
        const int s = kcc % 3;
        const uint32_t bs = sb + s * STG_STRIDE;
        #pragma unroll
        for (int i = 0; i < 8; i++) {                       // B fp32: 32 rows x 1KB
            const int idx = t + i * 256;
            const int r = idx >> 6, c16 = idx & 63;
            cp16(bs + r * 1024 + c16 * 16,
                 xb + ((size_t)(kcc * 32 + r) * HW_) * 4 + c16 * 16);
        }
        const uint32_t as = sb + A_STAGE_OFF + s * A_STRIDE;
        #pragma unroll
        for (int i = 0; i < 4; i++) {                       // A bf16 hi/lo: 2x128x64B
            const int idx = t + i * 256;
            const int half = idx >> 9, rr = (idx >> 2) & 127, c4 = idx & 3;
            const char* g = (half ? pAl : pAh) + ((size_t)rr * C_ + kcc * 32) * 2 + c4 * 16;
            cp16(as + half * 10240 + rr * 80 + c4 * 16, g);
        }
    };

    auto convert_chunk = [&](int kcc) {
        const char* stg = dsm + (kcc % 3) * STG_STRIDE;
        char* cvh = dsm + CONV_OFF + (kcc & 1) * CONV_SET;
        char* cvl = cvh + CONV_HALF;
        const int r = t >> 3;
        #pragma unroll
        for (int j = 0; j < 4; j++) {
            const int cb = (t & 7) * 8 + 64 * j;            // float index in row
            float4 v0 = *(const float4*)(stg + r * 1024 + cb * 4);
            float4 v1 = *(const float4*)(stg + r * 1024 + cb * 4 + 16);
            uint4 h, l;
            split2(v0.x, v0.y, h.x, l.x);
            split2(v0.z, v0.w, h.y, l.y);
            split2(v1.x, v1.y, h.z, l.z);
            split2(v1.z, v1.w, h.w, l.w);
            *(uint4*)(cvh + r * 528 + cb * 2) = h;
            *(uint4*)(cvl + r * 528 + cb * 2) = l;
        }
    };

    float acc[4][8][4];
    #pragma unroll
    for (int i = 0; i < 4; i++)
        #pragma unroll
        for (int j = 0; j < 8; j++)
            #pragma unroll
            for (int e = 0; e < 4; e++) acc[i][j][e] = 0.f;

    load_group(0); CP_COMMIT();
    load_group(1); CP_COMMIT();
    CP_WAIT1();
    __syncthreads();
    convert_chunk(0);
    __syncthreads();

    for (int kc = 0; kc < 8; kc++) {
        // ---- MMA phase: A stage kc%3, conv set kc&1 ----
        const uint32_t as  = sb + A_STAGE_OFF + (kc % 3) * A_STRIDE;
        const uint32_t cvb = sb + CONV_OFF + (kc & 1) * CONV_SET;
        #pragma unroll
        for (int kk = 0; kk < 2; kk++) {
            uint32_t ah[4][4], al[4][4], bh[4][4], bl[4][4];
            const uint32_t aoff = as + (uint32_t)(m64w + (lane & 15)) * 80
                                + kk * 32 + ((lane >> 4) * 16);
            #pragma unroll
            for (int mt = 0; mt < 4; mt++) {
                ldm4(ah[mt], aoff + mt * 16 * 80);
                ldm4(al[mt], aoff + 10240 + mt * 16 * 80);
            }
            const int g = lane >> 3;
            const uint32_t krow = (uint32_t)(kk * 16 + ((g & 1) << 3) + (lane & 7));
            const uint32_t boff = cvb + krow * 528 + (uint32_t)(n64w + ((g >> 1) << 3)) * 2;
            #pragma unroll
            for (int tp = 0; tp < 4; tp++) {
                ldm4t(bh[tp], boff + tp * 32);
                ldm4t(bl[tp], boff + CONV_HALF + tp * 32);
            }
            #pragma unroll
            for (int mt = 0; mt < 4; mt++) {
                #pragma unroll
                for (int tp = 0; tp < 4; tp++) {
                    mma_bf16(acc[mt][2 * tp],     ah[mt], &bh[tp][0]);
                    mma_bf16(acc[mt][2 * tp + 1], ah[mt], &bh[tp][2]);
                    mma_bf16(acc[mt][2 * tp],     ah[mt], &bl[tp][0]);
                    mma_bf16(acc[mt][2 * tp + 1], ah[mt], &bl[tp][2]);
                    mma_bf16(acc[mt][2 * tp],     al[mt], &bh[tp][0]);
                    mma_bf16(acc[mt][2 * tp + 1], al[mt], &bh[tp][2]);
                }
            }
        }
        // ---- pipeline bookkeeping ----
        if (kc + 2 < 8) load_group(kc + 2);
        CP_COMMIT();
        CP_WAIT1();                 // group kc+1 complete
        __syncthreads();            // publish cp data; conv[(kc+1)&1] free
        if (kc < 7) convert_chunk(kc + 1);
        __syncthreads();            // publish converted tiles
    }

    // ---- epilogue: direct stores; 4-lane groups cover aligned 32B sectors ----
    #pragma unroll
    for (int mt = 0; mt < 4; mt++) {
        const int o = m0 + m64w + mt * 16 + (lane >> 2);
        const float dv0 = g_dd[b * C_ + o];
        const float dv8 = g_dd[b * C_ + o + 8];
        float* r0 = out + ((size_t)(b * C_ + o)) * HW_;
        float* r8 = out + ((size_t)(b * C_ + o + 8)) * HW_;
        #pragma unroll
        for (int n = 0; n < 8; n++) {
            const int hw = n0 + n64w + n * 8 + (lane & 3) * 2;
            float2 v0, v1;
            v0.x = acc[mt][n][0] + dv0; v0.y = acc[mt][n][1] + dv0;
            v1.x = acc[mt][n][2] + dv8; v1.y = acc[mt][n][3] + dv8;
            *(float2*)(r0 + hw) = v0;
            *(float2*)(r8 + hw) = v1;
        }
    }
}

extern "C" void kernel_launch(void* const* d_in, const int* in_sizes, int n_in,
                              void* d_out, int out_size) {
    const float* x      = (const float*)d_in[0];
    const float* params = (const float*)d_in[1];
    const float* W      = (const float*)d_in[2];
    float* out          = (float*)d_out;

    cudaFuncSetAttribute(gemm_kernel, cudaFuncAttributeMaxDynamicSharedMemorySize, SMEM_BYTES);

    stats_kernel<<<dim3(C_, B_), 256>>>(x);
    transpose_kernel<<<2 * C_, 256>>>(W);
    prep_kernel<<<B_, 256>>>(params);
    gemm_kernel<<<dim3(HW_ / 256, C_ / 128, B_), 256, SMEM_BYTES>>>(x, out);
}